// round 5
// baseline (speedup 1.0000x reference)
#include <cuda_runtime.h>

// BinNormTrain: per-row nu s.t. sum_d sigmoid(x[d]+nu) == 64; out = sigmoid(x+nu).
// R5: proven EX2+RCP numerics (tanh.approx measured untrustworthy on sm_103a).
// Quad-rational sigmoid eval (one RCP per 4 elems, exact per-element s),
// secant slope (no q accumulation, one warp reduction per iter), Chebyshev
// bracket from sum/sumsq (no max/min reductions), balanced 1024x128 grid.

#ifndef BN_D
#define BN_D 256
#endif

static __device__ __forceinline__ float ex2_approx(float a) {
    float r; asm("ex2.approx.ftz.f32 %0, %1;" : "=f"(r) : "f"(a)); return r;
}
static __device__ __forceinline__ float rcp_approx(float a) {
    float r; asm("rcp.approx.ftz.f32 %0, %1;" : "=f"(r) : "f"(a)); return r;
}

static __device__ __forceinline__ float warp_sum(float v) {
    #pragma unroll
    for (int o = 16; o > 0; o >>= 1) v += __shfl_xor_sync(0xFFFFFFFFu, v, o);
    return v;  // bitwise-identical on all lanes
}

__global__ __launch_bounds__(128)
void binnorm_kernel(const float* __restrict__ x, float* __restrict__ out, int B) {
    const int lane   = threadIdx.x & 31;
    const int warp0  = (blockIdx.x * blockDim.x + threadIdx.x) >> 5;
    const int nwarps = (gridDim.x * blockDim.x) >> 5;
    const float L2E = 1.44269504f;

    for (int row = warp0; row < B; row += nwarps) {
        const float4* __restrict__ xr = reinterpret_cast<const float4*>(x + (size_t)row * BN_D);
        float4 v0 = xr[lane];
        float4 v1 = xr[lane + 32];
        float xs[8] = {v0.x, v0.y, v0.z, v0.w, v1.x, v1.y, v1.z, v1.w};

        // Row stats (2 reductions only).
        float sm = 0.f, sq = 0.f;
        #pragma unroll
        for (int i = 0; i < 8; ++i) { sm += xs[i]; sq = fmaf(xs[i], xs[i], sq); }
        sm = warp_sum(sm);
        sq = warp_sum(sq);

        const float m = sm * (1.0f / BN_D);
        // Chebyshev: (max-m)^2 <= sum (x-m)^2 = sq - 256 m^2  -> rigorous bracket.
        const float c = sqrtf(fmaxf(fmaf(-sm, m, sq), 0.f));
        float lo = -m - c - 7.0f;          // f(lo) <= 256*sig(-7)-64 < 0
        float hi = -m + c + 7.0f;          // f(hi) >= 256*sig(+7)-64 > 0

        const float var = fmaxf(sq * (1.0f / BN_D) - m * m, 0.f);
        const float g2  = fmaf(0.3926991f, var, 1.0f);
        const float rs  = rsqrtf(g2);
        // Logit-moment warm start: nu0 = -m - ln3 * sqrt(g2)
        float nu = fmaf(-1.0986123f * g2, rs, -m);
        nu = fminf(fmaxf(nu, lo), hi);
        const float fp0 = 48.0f * rs;      // analytic slope model  ~ sum s(1-s)

        float r[8];
        float fm_prev = 0.f, nu_prev = 0.f;
        #pragma unroll 1
        for (int it = 0; it < 16; ++it) {
            const float nl2e = -L2E * nu;
            float fsum = 0.f;
            // Quad-rational: one rcp per 4 elements, exact per-element sigmoids.
            #pragma unroll
            for (int q4 = 0; q4 < 8; q4 += 4) {
                float t0 = ex2_approx(fmaf(xs[q4+0], -L2E, nl2e));
                float t1 = ex2_approx(fmaf(xs[q4+1], -L2E, nl2e));
                float t2 = ex2_approx(fmaf(xs[q4+2], -L2E, nl2e));
                float t3 = ex2_approx(fmaf(xs[q4+3], -L2E, nl2e));
                float u0 = 1.0f + t0, u1 = 1.0f + t1, u2 = 1.0f + t2, u3 = 1.0f + t3;
                float p01 = u0 * u1, p23 = u2 * u3;
                float rq  = rcp_approx(p01 * p23);       // 1/(u0 u1 u2 u3)
                float t01 = p23 * rq, t23 = p01 * rq;    // 1/(u0 u1), 1/(u2 u3)
                float s0 = u1 * t01, s1 = u0 * t01;      // 1/u0, 1/u1
                float s2 = u3 * t23, s3 = u2 * t23;      // 1/u2, 1/u3
                r[q4+0] = s0; r[q4+1] = s1; r[q4+2] = s2; r[q4+3] = s3;
                fsum += (s0 + s1) + (s2 + s3);
            }
            float fm = warp_sum(fsum) - 64.0f;           // warp-uniform

            if (fm < 0.f) lo = nu; else hi = nu;

            float slope = (it == 0) ? fp0
                        : __fdividef(fm - fm_prev, nu - nu_prev);
            if (!(slope > 0.f)) slope = fp0;             // guards 0/neg/NaN/inf
            fm_prev = fm; nu_prev = nu;

            float nun = nu - __fdividef(fm, slope);
            if (!(nun > lo && nun < hi)) nun = 0.5f * (lo + hi);
            const float d = fabsf(nun - nu);
            nu = nun;
            if (d < 2.5e-4f) break;   // cached r at nu_prev: output nu-err <= ~3e-4
        }

        float4* __restrict__ orow = reinterpret_cast<float4*>(out + (size_t)row * BN_D);
        orow[lane]      = make_float4(r[0], r[1], r[2], r[3]);
        orow[lane + 32] = make_float4(r[4], r[5], r[6], r[7]);
    }
}

extern "C" void kernel_launch(void* const* d_in, const int* in_sizes, int n_in,
                              void* d_out, int out_size) {
    const float* x = (const float*)d_in[0];
    float* out = (float*)d_out;
    const int B = in_sizes[0] / BN_D;    // 16384 rows
    // 1024 blocks x 4 warps = 4096 warps -> exactly 4 rows/warp.
    // 6.92 blocks/SM fits in one wave at <=48 regs; near-perfect SM balance.
    binnorm_kernel<<<1024, 128>>>(x, out, B);
}

// round 6
// speedup vs baseline: 1.1429x; 1.1429x over previous
#include <cuda_runtime.h>

// BinNormTrain: per-row nu s.t. sum_d sigmoid(x[d]+nu) == 64; out = sigmoid(x+nu).
// R6: fixed-iteration structure. Warm start (e0 ~ 0.1) -> exactly 2 Newton
// iterations (e2 ~ 1e-3 worst case) -> one output pass computing accurate
// sigmoids s, the accurate Newton step d, and first-order-corrected outputs
// r = s + s(1-s) d   (residual O(d^2) <= ~1e-5 worst, ~3e-7 typical).
// No break, no bisection, no bracket bookkeeping, zero divergence.
// Quad-rational sigmoid (1 RCP / 4 elems) keeps MUFU at 10 warp-ops/pass.

#ifndef BN_D
#define BN_D 256
#endif

static __device__ __forceinline__ float ex2_approx(float a) {
    float r; asm("ex2.approx.ftz.f32 %0, %1;" : "=f"(r) : "f"(a)); return r;
}
static __device__ __forceinline__ float rcp_approx(float a) {
    float r; asm("rcp.approx.ftz.f32 %0, %1;" : "=f"(r) : "f"(a)); return r;
}
static __device__ __forceinline__ float warp_sum(float v) {
    #pragma unroll
    for (int o = 16; o > 0; o >>= 1) v += __shfl_xor_sync(0xFFFFFFFFu, v, o);
    return v;  // bitwise-identical on all lanes
}

// Quad-rational sigmoids of (xs[i]+nu) for 8 elems: writes s[0..7], accumulates
// f += sum s, q += sum s^2. 8 EX2 + 2 RCP MUFU ops total.
static __device__ __forceinline__ void sig8(const float* xs, float nl2e,
                                            float* s, float& f, float& q) {
    const float L2E = 1.44269504f;
    #pragma unroll
    for (int b = 0; b < 8; b += 4) {
        float t0 = ex2_approx(fmaf(xs[b+0], -L2E, nl2e));
        float t1 = ex2_approx(fmaf(xs[b+1], -L2E, nl2e));
        float t2 = ex2_approx(fmaf(xs[b+2], -L2E, nl2e));
        float t3 = ex2_approx(fmaf(xs[b+3], -L2E, nl2e));
        float u0 = 1.f + t0, u1 = 1.f + t1, u2 = 1.f + t2, u3 = 1.f + t3;
        float p01 = u0 * u1, p23 = u2 * u3;
        float rq  = rcp_approx(p01 * p23);
        float t01 = p23 * rq, t23 = p01 * rq;   // 1/(u0u1), 1/(u2u3)
        float s0 = u1 * t01, s1 = u0 * t01;     // 1/u0, 1/u1
        float s2 = u3 * t23, s3 = u2 * t23;     // 1/u2, 1/u3
        s[b+0] = s0; s[b+1] = s1; s[b+2] = s2; s[b+3] = s3;
        f += (s0 + s1) + (s2 + s3);
        q = fmaf(s0, s0, q); q = fmaf(s1, s1, q);
        q = fmaf(s2, s2, q); q = fmaf(s3, s3, q);
    }
}

__global__ __launch_bounds__(128, 7)
void binnorm_kernel(const float* __restrict__ x, float* __restrict__ out, int B) {
    const int lane   = threadIdx.x & 31;
    const int warp0  = (blockIdx.x * blockDim.x + threadIdx.x) >> 5;
    const int nwarps = (gridDim.x * blockDim.x) >> 5;
    const float L2E = 1.44269504f;

    for (int row = warp0; row < B; row += nwarps) {
        const float4* __restrict__ xr = reinterpret_cast<const float4*>(x + (size_t)row * BN_D);
        float4 v0 = xr[lane];
        float4 v1 = xr[lane + 32];
        float xs[8] = {v0.x, v0.y, v0.z, v0.w, v1.x, v1.y, v1.z, v1.w};

        // Row stats -> warm start + rigorous Chebyshev clamp bounds.
        float sm = 0.f, sq = 0.f;
        #pragma unroll
        for (int i = 0; i < 8; ++i) { sm += xs[i]; sq = fmaf(xs[i], xs[i], sq); }
        sm = warp_sum(sm);
        sq = warp_sum(sq);

        const float m = sm * (1.0f / BN_D);
        const float c = sqrtf(fmaxf(fmaf(-sm, m, sq), 0.f)); // (max|x-m|) <= c
        const float lo = -m - c - 7.0f;    // f(lo) < 0 guaranteed
        const float hi = -m + c + 7.0f;    // f(hi) > 0 guaranteed
        const float var = fmaxf(sq * (1.0f / BN_D) - m * m, 0.f);
        // Logit-moment warm start: nu0 = -m - ln3 * sqrt(1 + pi/8 * var)
        float nu = -m - 1.0986123f * sqrtf(fmaf(0.3926991f, var, 1.0f));
        nu = fminf(fmaxf(nu, lo), hi);

        float s[8];

        // Exactly 2 Newton iterations (no break, no divergence).
        #pragma unroll
        for (int it = 0; it < 2; ++it) {
            float f = 0.f, q = 0.f;
            sig8(xs, -L2E * nu, s, f, q);
            f = warp_sum(f);
            q = warp_sum(q);
            // fp = f - q = sum s(1-s) > 0 strictly.
            nu -= __fdividef(f - 64.0f, f - q);
            nu = fminf(fmaxf(nu, lo), hi);
        }

        // Output pass: accurate sigmoids at nu2, accurate step d, linear correction.
        float f = 0.f, q = 0.f;
        sig8(xs, -L2E * nu, s, f, q);
        f = warp_sum(f);
        q = warp_sum(q);
        const float d = -__fdividef(f - 64.0f, f - q);

        float r[8];
        #pragma unroll
        for (int i = 0; i < 8; ++i) {
            float p = s[i] * (1.0f - s[i]);      // sigma'
            r[i] = fmaf(p, d, s[i]);             // s(nu2+d) to first order
        }
        float4* __restrict__ orow = reinterpret_cast<float4*>(out + (size_t)row * BN_D);
        orow[lane]      = make_float4(r[0], r[1], r[2], r[3]);
        orow[lane + 32] = make_float4(r[4], r[5], r[6], r[7]);
    }
}

extern "C" void kernel_launch(void* const* d_in, const int* in_sizes, int n_in,
                              void* d_out, int out_size) {
    const float* x = (const float*)d_in[0];
    float* out = (float*)d_out;
    const int B = in_sizes[0] / BN_D;    // 16384 rows
    // 1024 blocks x 4 warps = 4096 warps -> EXACTLY 4 rows per warp (perfect
    // warp balance); ~7 blocks/SM resident in one wave, ~43% occ.
    binnorm_kernel<<<1024, 128>>>(x, out, B);
}